// round 1
// baseline (speedup 1.0000x reference)
#include <cuda_runtime.h>
#include <cuda_bf16.h>

#define N_NODES   200000
#define N_EDGES   400000
#define IN_CH     768
#define HID_CH    256
#define OUT_CH    256
#define NUM_GRAPHS 8000

// ---------------- scratch (device globals: no allocations allowed) ----------
__device__ int   g_is64;
__device__ int   g_edges[2 * N_EDGES];          // [src(E), dst(E)] as int32
__device__ int   g_batch[N_NODES];
__device__ float g_dinv[N_NODES];               // deg -> rsqrt(deg)
__device__ float g_h[(size_t)N_NODES * 256];    // GEMM output
__device__ float g_a[(size_t)N_NODES * 256];    // aggregated output

// ---------------- int64-vs-int32 detection + normalization ------------------
// If edge_index is int64, every value < 200000 => every odd 32-bit slot is 0.
__global__ void k_detect(const int* ei32) {
    __shared__ int any;
    if (threadIdx.x == 0) any = 0;
    __syncthreads();
    int idx = threadIdx.x * 3120 + 1;           // max 795601 < 800000 (safe for int32 case)
    if (ei32[idx] != 0) any = 1;
    __syncthreads();
    if (threadIdx.x == 0) g_is64 = (any == 0) ? 1 : 0;
}

__global__ void k_convert(const void* src, int* dst, int n) {
    int i = blockIdx.x * blockDim.x + threadIdx.x;
    if (i >= n) return;
    dst[i] = g_is64 ? (int)((const long long*)src)[i] : ((const int*)src)[i];
}

// ---------------- degree / normalization ------------------------------------
__global__ void k_deg_init() {
    int i = blockIdx.x * blockDim.x + threadIdx.x;
    if (i < N_NODES) g_dinv[i] = 1.0f;          // self-loop
}
__global__ void k_deg_accum() {
    int e = blockIdx.x * blockDim.x + threadIdx.x;
    if (e < N_EDGES) atomicAdd(&g_dinv[g_edges[N_EDGES + e]], 1.0f);
}
__global__ void k_deg_rsqrt() {
    int i = blockIdx.x * blockDim.x + threadIdx.x;
    if (i < N_NODES) g_dinv[i] = rsqrtf(g_dinv[i]);
}

// ---------------- SGEMM: C[M,256] = op(A[M,K]) @ B[K,256] -------------------
// BM=128, BN=128, BK=8, 256 threads, 8x8 microtile.
// FUSE: A element at (m,k) is relu(A[m,k] + bias[k])  (layer-2 input).
template<int K, bool FUSE>
__global__ __launch_bounds__(256, 2) void k_sgemm(
    const float* __restrict__ A, const float* __restrict__ B,
    const float* __restrict__ bias, float* __restrict__ C, int M)
{
    __shared__ float As[8][136];   // transposed A tile, padded
    __shared__ float Bs[8][128];

    const int tid  = threadIdx.x;
    const int bm   = blockIdx.x * 128;
    const int bn   = blockIdx.y * 128;
    const int aRow = tid >> 1;          // 0..127
    const int aK   = (tid & 1) * 4;     // 0 or 4
    const int bK   = tid >> 5;          // 0..7
    const int bN   = (tid & 31) * 4;    // 0..124
    const int tx   = tid & 15;
    const int ty   = tid >> 4;
    const bool aValid = (bm + aRow) < M;

    const float* Ap = A + (size_t)(bm + aRow) * K + aK;
    const float* Bp = B + (size_t)bK * 256 + bn + bN;

    float acc[8][8];
    #pragma unroll
    for (int i = 0; i < 8; i++)
        #pragma unroll
        for (int j = 0; j < 8; j++) acc[i][j] = 0.0f;

    float4 av = aValid ? *(const float4*)Ap : make_float4(0.f, 0.f, 0.f, 0.f);
    float4 bv = *(const float4*)Bp;
    if constexpr (FUSE) {
        float4 bb = *(const float4*)(bias + aK);
        av.x = fmaxf(av.x + bb.x, 0.f); av.y = fmaxf(av.y + bb.y, 0.f);
        av.z = fmaxf(av.z + bb.z, 0.f); av.w = fmaxf(av.w + bb.w, 0.f);
    }

    for (int k0 = 0; k0 < K; k0 += 8) {
        As[aK + 0][aRow] = av.x;
        As[aK + 1][aRow] = av.y;
        As[aK + 2][aRow] = av.z;
        As[aK + 3][aRow] = av.w;
        *(float4*)&Bs[bK][bN] = bv;
        __syncthreads();

        if (k0 + 8 < K) {                        // prefetch next tiles
            av = aValid ? *(const float4*)(Ap + k0 + 8) : make_float4(0.f, 0.f, 0.f, 0.f);
            bv = *(const float4*)(Bp + (size_t)(k0 + 8) * 256);
            if constexpr (FUSE) {
                float4 bb = *(const float4*)(bias + k0 + 8 + aK);
                av.x = fmaxf(av.x + bb.x, 0.f); av.y = fmaxf(av.y + bb.y, 0.f);
                av.z = fmaxf(av.z + bb.z, 0.f); av.w = fmaxf(av.w + bb.w, 0.f);
            }
        }

        #pragma unroll
        for (int kk = 0; kk < 8; kk++) {
            float a[8], b[8];
            *(float4*)&a[0] = *(const float4*)&As[kk][ty * 8];
            *(float4*)&a[4] = *(const float4*)&As[kk][ty * 8 + 4];
            *(float4*)&b[0] = *(const float4*)&Bs[kk][tx * 8];
            *(float4*)&b[4] = *(const float4*)&Bs[kk][tx * 8 + 4];
            #pragma unroll
            for (int i = 0; i < 8; i++)
                #pragma unroll
                for (int j = 0; j < 8; j++)
                    acc[i][j] = fmaf(a[i], b[j], acc[i][j]);
        }
        __syncthreads();
    }

    #pragma unroll
    for (int i = 0; i < 8; i++) {
        int row = bm + ty * 8 + i;
        if (row < M) {
            float4 v0 = make_float4(acc[i][0], acc[i][1], acc[i][2], acc[i][3]);
            float4 v1 = make_float4(acc[i][4], acc[i][5], acc[i][6], acc[i][7]);
            *(float4*)&C[(size_t)row * 256 + bn + tx * 8]     = v0;
            *(float4*)&C[(size_t)row * 256 + bn + tx * 8 + 4] = v1;
        }
    }
}

// ---------------- aggregation -----------------------------------------------
// Self-loop term writes the full buffer (doubles as the zero-init).
__global__ void k_selfloop(const float* __restrict__ h, float* __restrict__ a) {
    size_t i = (size_t)blockIdx.x * blockDim.x + threadIdx.x;   // over N*64 float4s
    if (i >= (size_t)N_NODES * 64) return;
    int v = (int)(i >> 6);
    float w = g_dinv[v]; w *= w;
    float4 x = ((const float4*)h)[i];
    x.x *= w; x.y *= w; x.z *= w; x.w *= w;
    ((float4*)a)[i] = x;
}

// One block per edge: out[dst] += h[src] * dinv[src]*dinv[dst]
__global__ void k_edge_agg(const float* __restrict__ h, float* __restrict__ a) {
    int e = blockIdx.x;
    int s = g_edges[e];
    int d = g_edges[N_EDGES + e];
    float w = g_dinv[s] * g_dinv[d];
    int c = threadIdx.x;
    atomicAdd(&a[(size_t)d * 256 + c], h[(size_t)s * 256 + c] * w);
}

// ---------------- pooling: batch is sorted -> binary search per graph -------
__global__ void k_pool(const float* __restrict__ a, const float* __restrict__ b2,
                       float* __restrict__ out) {
    int g = blockIdx.x;
    __shared__ int sLo, sHi;
    if (threadIdx.x == 0) {
        int lo = 0, hi = N_NODES;
        while (lo < hi) { int mid = (lo + hi) >> 1; if (g_batch[mid] < g) lo = mid + 1; else hi = mid; }
        sLo = lo;
        hi = N_NODES;
        while (lo < hi) { int mid = (lo + hi) >> 1; if (g_batch[mid] < g + 1) lo = mid + 1; else hi = mid; }
        sHi = lo;
    }
    __syncthreads();
    int c = threadIdx.x;
    float sum = 0.0f;
    for (int v = sLo; v < sHi; v++) sum += a[(size_t)v * 256 + c];
    int cnt = sHi - sLo;
    out[(size_t)g * 256 + c] = (cnt > 0) ? (sum / (float)cnt + b2[c]) : 0.0f;
}

// ---------------- launcher ---------------------------------------------------
extern "C" void kernel_launch(void* const* d_in, const int* in_sizes, int n_in,
                              void* d_out, int out_size) {
    const float* x    = (const float*)d_in[0];
    const float* W1   = (const float*)d_in[1];
    const float* b1   = (const float*)d_in[2];
    const float* W2   = (const float*)d_in[3];
    const float* b2   = (const float*)d_in[4];
    const void*  ei   = d_in[5];   // int64 or int32, detected at runtime
    const void*  bat  = d_in[6];
    float* out = (float*)d_out;

    float *ph, *pa;
    int *pe, *pb;
    cudaGetSymbolAddress((void**)&ph, g_h);
    cudaGetSymbolAddress((void**)&pa, g_a);
    cudaGetSymbolAddress((void**)&pe, g_edges);
    cudaGetSymbolAddress((void**)&pb, g_batch);

    k_detect<<<1, 256>>>((const int*)ei);
    k_convert<<<(2 * N_EDGES + 255) / 256, 256>>>(ei, pe, 2 * N_EDGES);
    k_convert<<<(N_NODES + 255) / 256, 256>>>(bat, pb, N_NODES);

    k_deg_init<<<(N_NODES + 255) / 256, 256>>>();
    k_deg_accum<<<(N_EDGES + 255) / 256, 256>>>();
    k_deg_rsqrt<<<(N_NODES + 255) / 256, 256>>>();

    dim3 gemmGrid((N_NODES + 127) / 128, 2);

    // layer 1: h = x @ W1 ; a = A_norm h ; (relu(a+b1) fused into next GEMM's A-load)
    k_sgemm<IN_CH, false><<<gemmGrid, 256>>>(x, W1, nullptr, ph, N_NODES);
    k_selfloop<<<(N_NODES * 64 + 255) / 256, 256>>>(ph, pa);
    k_edge_agg<<<N_EDGES, 256>>>(ph, pa);

    // layer 2: h = relu(a + b1) @ W2 ; a = A_norm h
    k_sgemm<HID_CH, true><<<gemmGrid, 256>>>(pa, W2, b1, ph, N_NODES);
    k_selfloop<<<(N_NODES * 64 + 255) / 256, 256>>>(ph, pa);
    k_edge_agg<<<N_EDGES, 256>>>(ph, pa);

    // mean-pool per graph, + b2 (empty graphs -> exact 0 per reference)
    k_pool<<<NUM_GRAPHS, 256>>>(pa, b2, out);
}

// round 2
// speedup vs baseline: 2.1583x; 2.1583x over previous
#include <cuda_runtime.h>
#include <cuda_bf16.h>
#include <cstdint>

#define N_NODES   200000
#define N_EDGES   400000
#define IN_CH     768
#define HID_CH    256
#define OUT_CH    256
#define NUM_GRAPHS 8000

// ---------------- scratch (device globals: no allocations allowed) ----------
__device__ int   g_is64;
__device__ int   g_edges[2 * N_EDGES];          // [src(E), dst(E)] as int32
__device__ int   g_batch[N_NODES];
__device__ float g_dinv[N_NODES];               // deg -> rsqrt(deg)
__device__ float g_h[(size_t)N_NODES * 256];    // GEMM output (pre-agg features)
__device__ float g_a[(size_t)N_NODES * 256];    // aggregated output
__device__ __nv_bfloat16 g_w1hi[256 * IN_CH];   // W1^T split  [N][K]
__device__ __nv_bfloat16 g_w1lo[256 * IN_CH];
__device__ __nv_bfloat16 g_w2hi[256 * HID_CH];  // W2^T split
__device__ __nv_bfloat16 g_w2lo[256 * HID_CH];

// ---------------- int64-vs-int32 detection + normalization ------------------
__global__ void k_detect(const int* ei32) {
    __shared__ int any;
    if (threadIdx.x == 0) any = 0;
    __syncthreads();
    int idx = threadIdx.x * 3120 + 1;           // max 795601 < 800000 (safe for int32 case)
    if (ei32[idx] != 0) any = 1;
    __syncthreads();
    if (threadIdx.x == 0) g_is64 = (any == 0) ? 1 : 0;
}

__global__ void k_convert(const void* src, int* dst, int n) {
    int i = blockIdx.x * blockDim.x + threadIdx.x;
    if (i >= n) return;
    dst[i] = g_is64 ? (int)((const long long*)src)[i] : ((const int*)src)[i];
}

// ---------------- degree / normalization ------------------------------------
__global__ void k_deg_init() {
    int i = blockIdx.x * blockDim.x + threadIdx.x;
    if (i < N_NODES) g_dinv[i] = 1.0f;          // self-loop
}
__global__ void k_deg_accum() {
    int e = blockIdx.x * blockDim.x + threadIdx.x;
    if (e < N_EDGES) atomicAdd(&g_dinv[g_edges[N_EDGES + e]], 1.0f);
}
__global__ void k_deg_rsqrt() {
    int i = blockIdx.x * blockDim.x + threadIdx.x;
    if (i < N_NODES) g_dinv[i] = rsqrtf(g_dinv[i]);
}

// ---------------- weight transpose + bf16 hi/lo split ------------------------
__global__ void k_wprep(const float* __restrict__ W, __nv_bfloat16* hi,
                        __nv_bfloat16* lo, int K, int N) {
    int i = blockIdx.x * blockDim.x + threadIdx.x;
    if (i >= K * N) return;
    int k = i / N, n = i % N;
    float w = W[i];
    __nv_bfloat16 h = __float2bfloat16_rn(w);
    __nv_bfloat16 l = __float2bfloat16_rn(w - __bfloat162float(h));
    hi[(size_t)n * K + k] = h;
    lo[(size_t)n * K + k] = l;
}

// ---------------- tensor-core GEMM -------------------------------------------
// C[M,256] = op(A[M,K]) @ W[K,256], bf16 hi/lo split (3 HMMA products), fp32 acc.
// Block tile 128x128, BK=32, 256 threads = 8 warps (4M x 2N), warp tile 32x64.
// Epilogue writes H = C and Aout = C * dinv[row]^2 (fused self-loop init).
// FUSE: A element = relu(A[m,k] + bias[k])   (layer-2 input path).

__device__ __forceinline__ void ldsm4(uint32_t r[4], uint32_t addr) {
    asm volatile("ldmatrix.sync.aligned.m8n8.x4.shared.b16 {%0,%1,%2,%3}, [%4];"
        : "=r"(r[0]), "=r"(r[1]), "=r"(r[2]), "=r"(r[3]) : "r"(addr));
}
__device__ __forceinline__ void mma16816(float c[4], const uint32_t a[4], const uint32_t b[2]) {
    asm volatile(
        "mma.sync.aligned.m16n8k16.row.col.f32.bf16.bf16.f32 "
        "{%0,%1,%2,%3}, {%4,%5,%6,%7}, {%8,%9}, {%0,%1,%2,%3};"
        : "+f"(c[0]), "+f"(c[1]), "+f"(c[2]), "+f"(c[3])
        : "r"(a[0]), "r"(a[1]), "r"(a[2]), "r"(a[3]), "r"(b[0]), "r"(b[1]));
}

#define BKP 40   // padded BK (bf16 elems): row stride 80B -> conflict-free ldmatrix

template<int K, bool FUSE>
__global__ __launch_bounds__(256) void k_gemm_tc(
    const float* __restrict__ A,
    const __nv_bfloat16* __restrict__ BHi, const __nv_bfloat16* __restrict__ BLo,
    const float* __restrict__ bias,
    float* __restrict__ H, float* __restrict__ Aout, int M)
{
    __shared__ __align__(16) __nv_bfloat16 Ahi[128][BKP];
    __shared__ __align__(16) __nv_bfloat16 Alo[128][BKP];
    __shared__ __align__(16) __nv_bfloat16 Bhi[128][BKP];
    __shared__ __align__(16) __nv_bfloat16 Blo[128][BKP];

    const int tid  = threadIdx.x;
    const int lane = tid & 31;
    const int wid  = tid >> 5;
    const int bm   = blockIdx.y * 128;
    const int bn   = blockIdx.x * 128;
    const int wm   = (wid & 3) * 32;
    const int wn   = (wid >> 2) * 64;

    // global load mapping: thread -> (row = tid/2, k half = (tid&1)*16)
    const int gRow  = tid >> 1;
    const int gKoff = (tid & 1) * 16;
    const bool aValid = (bm + gRow) < M;
    const float* Ap = A + (size_t)(bm + gRow) * K + gKoff;
    const __nv_bfloat16* BHp = BHi + (size_t)(bn + gRow) * K + gKoff;
    const __nv_bfloat16* BLp = BLo + (size_t)(bn + gRow) * K + gKoff;

    // ldmatrix per-lane shared addresses
    const uint32_t aHiB = (uint32_t)__cvta_generic_to_shared(&Ahi[0][0]);
    const uint32_t aLoB = (uint32_t)__cvta_generic_to_shared(&Alo[0][0]);
    const uint32_t bHiB = (uint32_t)__cvta_generic_to_shared(&Bhi[0][0]);
    const uint32_t bLoB = (uint32_t)__cvta_generic_to_shared(&Blo[0][0]);
    const uint32_t aOff = (uint32_t)(wm + (lane & 15)) * (BKP * 2) + ((lane >> 4) << 4);
    const uint32_t bOff = (uint32_t)(wn + (lane & 7) + ((lane >> 4) & 1) * 8) * (BKP * 2)
                        + (((lane >> 3) & 1) << 4);

    float acc[2][8][4];
    #pragma unroll
    for (int mt = 0; mt < 2; mt++)
        #pragma unroll
        for (int nt = 0; nt < 8; nt++)
            #pragma unroll
            for (int j = 0; j < 4; j++) acc[mt][nt][j] = 0.0f;

    constexpr int KT = K / 32;
    float4 aReg[4];
    uint4  bhReg[2], blReg[2];

    // prefetch tile 0
    #pragma unroll
    for (int i = 0; i < 4; i++) {
        float4 v = aValid ? *(const float4*)(Ap + 4 * i) : make_float4(0.f, 0.f, 0.f, 0.f);
        if constexpr (FUSE) {
            float4 bb = *(const float4*)(bias + gKoff + 4 * i);
            v.x = fmaxf(v.x + bb.x, 0.f); v.y = fmaxf(v.y + bb.y, 0.f);
            v.z = fmaxf(v.z + bb.z, 0.f); v.w = fmaxf(v.w + bb.w, 0.f);
            if (!aValid) v = make_float4(0.f, 0.f, 0.f, 0.f);
        }
        aReg[i] = v;
    }
    #pragma unroll
    for (int j = 0; j < 2; j++) {
        bhReg[j] = *(const uint4*)(BHp + 8 * j);
        blReg[j] = *(const uint4*)(BLp + 8 * j);
    }

    for (int kt = 0; kt < KT; kt++) {
        // stage registers -> smem (A: split fp32 -> hi/lo bf16)
        #pragma unroll
        for (int i = 0; i < 4; i++) {
            float4 v = aReg[i];
            __nv_bfloat16 hx = __float2bfloat16_rn(v.x);
            __nv_bfloat16 hy = __float2bfloat16_rn(v.y);
            __nv_bfloat16 hz = __float2bfloat16_rn(v.z);
            __nv_bfloat16 hw = __float2bfloat16_rn(v.w);
            __nv_bfloat162 h0; h0.x = hx; h0.y = hy;
            __nv_bfloat162 h1; h1.x = hz; h1.y = hw;
            __nv_bfloat162 l0; l0.x = __float2bfloat16_rn(v.x - __bfloat162float(hx));
                               l0.y = __float2bfloat16_rn(v.y - __bfloat162float(hy));
            __nv_bfloat162 l1; l1.x = __float2bfloat16_rn(v.z - __bfloat162float(hz));
                               l1.y = __float2bfloat16_rn(v.w - __bfloat162float(hw));
            *(__nv_bfloat162*)&Ahi[gRow][gKoff + 4 * i]     = h0;
            *(__nv_bfloat162*)&Ahi[gRow][gKoff + 4 * i + 2] = h1;
            *(__nv_bfloat162*)&Alo[gRow][gKoff + 4 * i]     = l0;
            *(__nv_bfloat162*)&Alo[gRow][gKoff + 4 * i + 2] = l1;
        }
        #pragma unroll
        for (int j = 0; j < 2; j++) {
            *(uint4*)&Bhi[gRow][gKoff + 8 * j] = bhReg[j];
            *(uint4*)&Blo[gRow][gKoff + 8 * j] = blReg[j];
        }
        __syncthreads();

        if (kt + 1 < KT) {  // prefetch next (overlaps with mma below)
            const int ko = (kt + 1) * 32;
            #pragma unroll
            for (int i = 0; i < 4; i++) {
                float4 v = aValid ? *(const float4*)(Ap + ko + 4 * i)
                                  : make_float4(0.f, 0.f, 0.f, 0.f);
                if constexpr (FUSE) {
                    float4 bb = *(const float4*)(bias + ko + gKoff + 4 * i);
                    v.x = fmaxf(v.x + bb.x, 0.f); v.y = fmaxf(v.y + bb.y, 0.f);
                    v.z = fmaxf(v.z + bb.z, 0.f); v.w = fmaxf(v.w + bb.w, 0.f);
                    if (!aValid) v = make_float4(0.f, 0.f, 0.f, 0.f);
                }
                aReg[i] = v;
            }
            #pragma unroll
            for (int j = 0; j < 2; j++) {
                bhReg[j] = *(const uint4*)(BHp + ko + 8 * j);
                blReg[j] = *(const uint4*)(BLp + ko + 8 * j);
            }
        }

        // compute: 2 k16 steps
        #pragma unroll
        for (int kk = 0; kk < 2; kk++) {
            const uint32_t ko = kk * 32;   // 16 bf16 = 32 bytes
            uint32_t afh[2][4], afl[2][4], bfh[4][4], bfl[4][4];
            #pragma unroll
            for (int mt = 0; mt < 2; mt++) {
                ldsm4(afh[mt], aHiB + aOff + mt * (16 * BKP * 2) + ko);
                ldsm4(afl[mt], aLoB + aOff + mt * (16 * BKP * 2) + ko);
            }
            #pragma unroll
            for (int np = 0; np < 4; np++) {
                ldsm4(bfh[np], bHiB + bOff + np * (16 * BKP * 2) + ko);
                ldsm4(bfl[np], bLoB + bOff + np * (16 * BKP * 2) + ko);
            }
            #pragma unroll
            for (int mt = 0; mt < 2; mt++)
                #pragma unroll
                for (int nt = 0; nt < 8; nt++) {
                    const uint32_t* bh = &bfh[nt >> 1][(nt & 1) * 2];
                    const uint32_t* bl = &bfl[nt >> 1][(nt & 1) * 2];
                    mma16816(acc[mt][nt], afh[mt], bh);
                    mma16816(acc[mt][nt], afh[mt], bl);
                    mma16816(acc[mt][nt], afl[mt], bh);
                }
        }
        __syncthreads();
    }

    // epilogue: H = C ; Aout = C * dinv[row]^2  (fused self-loop)
    #pragma unroll
    for (int mt = 0; mt < 2; mt++) {
        int r0 = bm + wm + mt * 16 + (lane >> 2);
        int r1 = r0 + 8;
        float w0 = 0.f, w1 = 0.f;
        if (r0 < M) { w0 = g_dinv[r0]; w0 *= w0; }
        if (r1 < M) { w1 = g_dinv[r1]; w1 *= w1; }
        #pragma unroll
        for (int nt = 0; nt < 8; nt++) {
            int cn = bn + wn + nt * 8 + (lane & 3) * 2;
            if (r0 < M) {
                float2 v = make_float2(acc[mt][nt][0], acc[mt][nt][1]);
                *(float2*)&H[(size_t)r0 * 256 + cn] = v;
                *(float2*)&Aout[(size_t)r0 * 256 + cn] = make_float2(v.x * w0, v.y * w0);
            }
            if (r1 < M) {
                float2 v = make_float2(acc[mt][nt][2], acc[mt][nt][3]);
                *(float2*)&H[(size_t)r1 * 256 + cn] = v;
                *(float2*)&Aout[(size_t)r1 * 256 + cn] = make_float2(v.x * w1, v.y * w1);
            }
        }
    }
}

// ---------------- edge aggregation: warp per edge, red.v4 -------------------
__device__ __forceinline__ void red4(float* p, float x, float y, float z, float w) {
    asm volatile("red.global.add.v4.f32 [%0], {%1,%2,%3,%4};"
        :: "l"(p), "f"(x), "f"(y), "f"(z), "f"(w) : "memory");
}

__global__ void k_edge_agg(const float* __restrict__ h, float* __restrict__ a) {
    int e = blockIdx.x * 8 + (threadIdx.x >> 5);
    if (e >= N_EDGES) return;
    int lane = threadIdx.x & 31;
    int s = g_edges[e];
    int d = g_edges[N_EDGES + e];
    float w = g_dinv[s] * g_dinv[d];
    const float4* hp = (const float4*)(h + (size_t)s * 256);
    float* ap = a + (size_t)d * 256;
    #pragma unroll
    for (int j = 0; j < 2; j++) {
        float4 v = hp[lane + 32 * j];
        red4(ap + (size_t)(lane + 32 * j) * 4, v.x * w, v.y * w, v.z * w, v.w * w);
    }
}

// ---------------- pooling: batch is sorted -> binary search per graph -------
__global__ void k_pool(const float* __restrict__ a, const float* __restrict__ b2,
                       float* __restrict__ out) {
    int g = blockIdx.x;
    __shared__ int sLo, sHi;
    if (threadIdx.x == 0) {
        int lo = 0, hi = N_NODES;
        while (lo < hi) { int mid = (lo + hi) >> 1; if (g_batch[mid] < g) lo = mid + 1; else hi = mid; }
        sLo = lo;
        hi = N_NODES;
        while (lo < hi) { int mid = (lo + hi) >> 1; if (g_batch[mid] < g + 1) lo = mid + 1; else hi = mid; }
        sHi = lo;
    }
    __syncthreads();
    int c = threadIdx.x;
    float sum = 0.0f;
    for (int v = sLo; v < sHi; v++) sum += a[(size_t)v * 256 + c];
    int cnt = sHi - sLo;
    out[(size_t)g * 256 + c] = (cnt > 0) ? (sum / (float)cnt + b2[c]) : 0.0f;
}

// ---------------- launcher ---------------------------------------------------
extern "C" void kernel_launch(void* const* d_in, const int* in_sizes, int n_in,
                              void* d_out, int out_size) {
    const float* x    = (const float*)d_in[0];
    const float* W1   = (const float*)d_in[1];
    const float* b1   = (const float*)d_in[2];
    const float* W2   = (const float*)d_in[3];
    const float* b2   = (const float*)d_in[4];
    const void*  ei   = d_in[5];
    const void*  bat  = d_in[6];
    float* out = (float*)d_out;

    float *ph, *pa;
    int *pe, *pb;
    __nv_bfloat16 *pw1h, *pw1l, *pw2h, *pw2l;
    cudaGetSymbolAddress((void**)&ph, g_h);
    cudaGetSymbolAddress((void**)&pa, g_a);
    cudaGetSymbolAddress((void**)&pe, g_edges);
    cudaGetSymbolAddress((void**)&pb, g_batch);
    cudaGetSymbolAddress((void**)&pw1h, g_w1hi);
    cudaGetSymbolAddress((void**)&pw1l, g_w1lo);
    cudaGetSymbolAddress((void**)&pw2h, g_w2hi);
    cudaGetSymbolAddress((void**)&pw2l, g_w2lo);

    k_detect<<<1, 256>>>((const int*)ei);
    k_convert<<<(2 * N_EDGES + 255) / 256, 256>>>(ei, pe, 2 * N_EDGES);
    k_convert<<<(N_NODES + 255) / 256, 256>>>(bat, pb, N_NODES);

    k_deg_init<<<(N_NODES + 255) / 256, 256>>>();
    k_deg_accum<<<(N_EDGES + 255) / 256, 256>>>();
    k_deg_rsqrt<<<(N_NODES + 255) / 256, 256>>>();

    k_wprep<<<(IN_CH * 256 + 255) / 256, 256>>>(W1, pw1h, pw1l, IN_CH, HID_CH);
    k_wprep<<<(HID_CH * 256 + 255) / 256, 256>>>(W2, pw2h, pw2l, HID_CH, OUT_CH);

    // grid: N-tile fastest so twin CTAs sharing an A tile are launch-adjacent (L2 reuse)
    dim3 gemmGrid(2, (N_NODES + 127) / 128);

    // layer 1
    k_gemm_tc<IN_CH, false><<<gemmGrid, 256>>>(x, pw1h, pw1l, nullptr, ph, pa, N_NODES);
    k_edge_agg<<<(N_EDGES + 7) / 8, 256>>>(ph, pa);

    // layer 2 (relu(a + b1) fused into A load)
    k_gemm_tc<HID_CH, true><<<gemmGrid, 256>>>(pa, pw2h, pw2l, b1, ph, pa, N_NODES);
    k_edge_agg<<<(N_EDGES + 7) / 8, 256>>>(ph, pa);

    k_pool<<<NUM_GRAPHS, 256>>>(pa, b2, out);
}

// round 4
// speedup vs baseline: 2.1692x; 1.0051x over previous
#include <cuda_runtime.h>
#include <cuda_bf16.h>
#include <cstdint>

#define N_NODES   200000
#define N_EDGES   400000
#define IN_CH     768
#define HID_CH    256
#define NUM_GRAPHS 8000

// ---------------- scratch (device globals: no allocations allowed) ----------
__device__ int   g_is64;
__device__ int   g_edges[2 * N_EDGES];          // [src(E), dst(E)] as int32
__device__ int   g_batch[N_NODES];
__device__ int   g_indeg[N_NODES];
__device__ int   g_rowptr[N_NODES + 1];
__device__ int   g_cursor[N_NODES];
__device__ int   g_csrc[N_EDGES];               // CSR-by-dst: src ids
__device__ float g_dinv[N_NODES];               // rsqrt(1 + indeg)
__device__ float g_h[(size_t)N_NODES * 256];    // GEMM output (pre-agg features)
__device__ float g_a[(size_t)N_NODES * 256];    // aggregated output
__device__ __nv_bfloat16 g_w1hi[256 * IN_CH];   // W^T hi/lo splits, [n][k] K-major
__device__ __nv_bfloat16 g_w1lo[256 * IN_CH];
__device__ __nv_bfloat16 g_w2hi[256 * HID_CH];
__device__ __nv_bfloat16 g_w2lo[256 * HID_CH];

// ---------------- setup ------------------------------------------------------
__global__ void k_detect(const int* ei32) {
    __shared__ int any;
    if (threadIdx.x == 0) any = 0;
    __syncthreads();
    int idx = threadIdx.x * 3120 + 1;           // max 795601 < 800000 (safe if int32)
    if (ei32[idx] != 0) any = 1;
    __syncthreads();
    if (threadIdx.x == 0) g_is64 = (any == 0) ? 1 : 0;
}

__global__ void k_convert_all(const void* ei, const void* bat) {
    int i = blockIdx.x * blockDim.x + threadIdx.x;
    bool is64 = (g_is64 != 0);
    if (i < 2 * N_EDGES)
        g_edges[i] = is64 ? (int)((const long long*)ei)[i] : ((const int*)ei)[i];
    if (i < N_NODES) {
        g_batch[i] = is64 ? (int)((const long long*)bat)[i] : ((const int*)bat)[i];
        g_indeg[i] = 0;
    }
}

__global__ void k_deg_accum() {
    int e = blockIdx.x * blockDim.x + threadIdx.x;
    if (e < N_EDGES) atomicAdd(&g_indeg[g_edges[N_EDGES + e]], 1);
}

// single-block scan: rowptr = exclusive_scan(indeg), cursor = rowptr, dinv = rsqrt(1+deg)
__global__ void k_scan() {
    __shared__ int wsum[32];
    __shared__ int base;
    const int tid = threadIdx.x, lane = tid & 31, wid = tid >> 5;
    if (tid == 0) base = 0;
    __syncthreads();
    for (int c0 = 0; c0 < N_NODES; c0 += 1024) {
        int i = c0 + tid;
        int v = (i < N_NODES) ? g_indeg[i] : 0;
        int x = v;
        #pragma unroll
        for (int o = 1; o < 32; o <<= 1) {
            int y = __shfl_up_sync(0xffffffffu, x, o);
            if (lane >= o) x += y;
        }
        if (lane == 31) wsum[wid] = x;
        __syncthreads();
        if (wid == 0) {
            int s = wsum[lane];
            #pragma unroll
            for (int o = 1; o < 32; o <<= 1) {
                int y = __shfl_up_sync(0xffffffffu, s, o);
                if (lane >= o) s += y;
            }
            wsum[lane] = s;
        }
        __syncthreads();
        int pre = base + (wid ? wsum[wid - 1] : 0) + x - v;
        if (i < N_NODES) {
            g_rowptr[i] = pre;
            g_cursor[i] = pre;
            g_dinv[i] = rsqrtf(1.0f + (float)v);
        }
        __syncthreads();
        if (tid == 0) base += wsum[31];
        __syncthreads();
    }
    if (threadIdx.x == 0) g_rowptr[N_NODES] = base;
}

// CSR scatter + weight transpose/split, one kernel (grid covers 400000 threads)
__global__ void k_fill_wprep(const float* __restrict__ W1, const float* __restrict__ W2) {
    int i = blockIdx.x * blockDim.x + threadIdx.x;
    if (i < N_EDGES) {
        int s = g_edges[i], d = g_edges[N_EDGES + i];
        int pos = atomicAdd(&g_cursor[d], 1);
        g_csrc[pos] = s;
    }
    if (i < IN_CH * 256) {
        int k = i / 256, n = i % 256;
        float w = W1[i];
        __nv_bfloat16 h = __float2bfloat16_rn(w);
        g_w1hi[(size_t)n * IN_CH + k] = h;
        g_w1lo[(size_t)n * IN_CH + k] = __float2bfloat16_rn(w - __bfloat162float(h));
    } else {
        int j = i - IN_CH * 256;
        if (j < HID_CH * 256) {
            int k = j / 256, n = j % 256;
            float w = W2[j];
            __nv_bfloat16 h = __float2bfloat16_rn(w);
            g_w2hi[(size_t)n * HID_CH + k] = h;
            g_w2lo[(size_t)n * HID_CH + k] = __float2bfloat16_rn(w - __bfloat162float(h));
        }
    }
}

// ---------------- GEMM: mma.sync bf16 3-product split, 2-stage pipeline ------
__device__ __forceinline__ void ldsm4(uint32_t r[4], uint32_t addr) {
    asm volatile("ldmatrix.sync.aligned.m8n8.x4.shared.b16 {%0,%1,%2,%3}, [%4];"
        : "=r"(r[0]), "=r"(r[1]), "=r"(r[2]), "=r"(r[3]) : "r"(addr));
}
__device__ __forceinline__ void mma16816(float c[4], const uint32_t a[4], const uint32_t b[2]) {
    asm volatile(
        "mma.sync.aligned.m16n8k16.row.col.f32.bf16.bf16.f32 "
        "{%0,%1,%2,%3}, {%4,%5,%6,%7}, {%8,%9}, {%0,%1,%2,%3};"
        : "+f"(c[0]), "+f"(c[1]), "+f"(c[2]), "+f"(c[3])
        : "r"(a[0]), "r"(a[1]), "r"(a[2]), "r"(a[3]), "r"(b[0]), "r"(b[1]));
}
__device__ __forceinline__ void cpasync16(uint32_t dst, const void* src) {
    asm volatile("cp.async.cg.shared.global [%0], [%1], 16;" :: "r"(dst), "l"(src));
}
__device__ __forceinline__ uint32_t smem_u32(const void* p) {
    uint32_t a;
    asm("{ .reg .u64 t; cvta.to.shared.u64 t, %1; cvt.u32.u64 %0, t; }" : "=r"(a) : "l"(p));
    return a;
}

#define BKP 40                       // padded BK row (bf16): 80B stride
#define ST_BYTES (4 * 128 * BKP * 2) // 40960 per stage
#define OFF_AHI 0
#define OFF_ALO (128 * BKP * 2)
#define OFF_BHI (2 * 128 * BKP * 2)
#define OFF_BLO (3 * 128 * BKP * 2)
#define SMEM_DYN (2 * ST_BYTES)      // 81920

// C[M,256] = op(A[M,K]) @ W[K,256]; block 128x128, 8 warps (4M x 2N), warp 32x64.
// FUSE: A element = relu(A[m,k] + bias[k]). Epilogue writes H only.
template<int K, bool FUSE>
__global__ __launch_bounds__(256) void k_gemm_tc(
    const float* __restrict__ A,
    const __nv_bfloat16* __restrict__ BHi, const __nv_bfloat16* __restrict__ BLo,
    const float* __restrict__ bias, float* __restrict__ H, int M)
{
    extern __shared__ __align__(16) char smem[];
    const uint32_t sb = smem_u32(smem);

    const int tid  = threadIdx.x;
    const int lane = tid & 31;
    const int wid  = tid >> 5;
    const int bn   = blockIdx.x * 128;
    const int bm   = blockIdx.y * 128;
    const int wm   = (wid & 3) * 32;
    const int wn   = (wid >> 2) * 64;

    // loader mapping: row = tid>>1 (0..127), half = tid&1 (16 floats / 32B bf16)
    const int gRow  = tid >> 1;
    const int half  = tid & 1;
    const bool aValid = (bm + gRow) < M;
    const float* Ap = A + (size_t)(bm + gRow) * K + half * 16;
    const __nv_bfloat16* BHp = BHi + (size_t)(bn + gRow) * K + half * 16;
    const __nv_bfloat16* BLp = BLo + (size_t)(bn + gRow) * K + half * 16;
    const uint32_t stsOff = (uint32_t)gRow * (BKP * 2) + half * 32;

    // ldmatrix per-lane addresses (byte offsets within each array)
    const uint32_t aOff = (uint32_t)(wm + (lane & 15)) * (BKP * 2) + ((lane >> 4) << 4);
    const uint32_t bOff = (uint32_t)(wn + (lane & 7) + ((lane >> 4) & 1) * 8) * (BKP * 2)
                        + (((lane >> 3) & 1) << 4);

    float acc[2][8][4];
    #pragma unroll
    for (int mt = 0; mt < 2; mt++)
        #pragma unroll
        for (int nt = 0; nt < 8; nt++)
            #pragma unroll
            for (int j = 0; j < 4; j++) acc[mt][nt][j] = 0.0f;

    constexpr int KT = K / 32;

    float4 aReg[4];
    auto loadA = [&](int kt) {
        #pragma unroll
        for (int i = 0; i < 4; i++) {
            float4 t = aValid ? *(const float4*)(Ap + kt * 32 + 4 * i)
                              : make_float4(0.f, 0.f, 0.f, 0.f);
            if constexpr (FUSE) {
                float4 bb = *(const float4*)(bias + kt * 32 + half * 16 + 4 * i);
                t.x = fmaxf(t.x + bb.x, 0.f); t.y = fmaxf(t.y + bb.y, 0.f);
                t.z = fmaxf(t.z + bb.z, 0.f); t.w = fmaxf(t.w + bb.w, 0.f);
                if (!aValid) t = make_float4(0.f, 0.f, 0.f, 0.f);
            }
            aReg[i] = t;
        }
    };
    auto stsA = [&](uint32_t stage) {
        uint32_t hw[8], lw[8];
        #pragma unroll
        for (int i = 0; i < 4; i++) {
            float4 v = aReg[i];
            __nv_bfloat16 b0 = __float2bfloat16_rn(v.x);
            __nv_bfloat16 b1 = __float2bfloat16_rn(v.y);
            __nv_bfloat16 b2 = __float2bfloat16_rn(v.z);
            __nv_bfloat16 b3 = __float2bfloat16_rn(v.w);
            __nv_bfloat162 h0; h0.x = b0; h0.y = b1;
            __nv_bfloat162 h1; h1.x = b2; h1.y = b3;
            __nv_bfloat162 l0;
            l0.x = __float2bfloat16_rn(v.x - __bfloat162float(b0));
            l0.y = __float2bfloat16_rn(v.y - __bfloat162float(b1));
            __nv_bfloat162 l1;
            l1.x = __float2bfloat16_rn(v.z - __bfloat162float(b2));
            l1.y = __float2bfloat16_rn(v.w - __bfloat162float(b3));
            hw[2 * i] = *(uint32_t*)&h0; hw[2 * i + 1] = *(uint32_t*)&h1;
            lw[2 * i] = *(uint32_t*)&l0; lw[2 * i + 1] = *(uint32_t*)&l1;
        }
        uint32_t d = stage + OFF_AHI + stsOff;
        asm volatile("st.shared.v4.b32 [%0], {%1,%2,%3,%4};"
                     :: "r"(d), "r"(hw[0]), "r"(hw[1]), "r"(hw[2]), "r"(hw[3]) : "memory");
        asm volatile("st.shared.v4.b32 [%0], {%1,%2,%3,%4};"
                     :: "r"(d + 16), "r"(hw[4]), "r"(hw[5]), "r"(hw[6]), "r"(hw[7]) : "memory");
        d = stage + OFF_ALO + stsOff;
        asm volatile("st.shared.v4.b32 [%0], {%1,%2,%3,%4};"
                     :: "r"(d), "r"(lw[0]), "r"(lw[1]), "r"(lw[2]), "r"(lw[3]) : "memory");
        asm volatile("st.shared.v4.b32 [%0], {%1,%2,%3,%4};"
                     :: "r"(d + 16), "r"(lw[4]), "r"(lw[5]), "r"(lw[6]), "r"(lw[7]) : "memory");
    };
    auto cpB = [&](int kt, uint32_t stage) {
        cpasync16(stage + OFF_BHI + stsOff,      BHp + kt * 32);
        cpasync16(stage + OFF_BHI + stsOff + 16, BHp + kt * 32 + 8);
        cpasync16(stage + OFF_BLO + stsOff,      BLp + kt * 32);
        cpasync16(stage + OFF_BLO + stsOff + 16, BLp + kt * 32 + 8);
        asm volatile("cp.async.commit_group;" ::: "memory");
    };

    // prologue: stage 0 gets A(0)+B(0)
    loadA(0);
    cpB(0, sb);
    stsA(sb);

    for (int kt = 0; kt < KT; kt++) {
        const uint32_t cur = sb + (kt & 1) * ST_BYTES;
        const uint32_t nxt = sb + ((kt + 1) & 1) * ST_BYTES;

        asm volatile("cp.async.wait_group 0;" ::: "memory");
        __syncthreads();

        if (kt + 1 < KT) {
            loadA(kt + 1);          // LDG in flight under the mma loop
            cpB(kt + 1, nxt);       // async into the freed stage
        }

        #pragma unroll
        for (int kk = 0; kk < 2; kk++) {
            const uint32_t ko = kk * 32;
            uint32_t afh[2][4], afl[2][4], bfh[4][4], bfl[4][4];
            #pragma unroll
            for (int mt = 0; mt < 2; mt++) {
                ldsm4(afh[mt], cur + OFF_AHI + aOff + mt * (16 * BKP * 2) + ko);
                ldsm4(afl[mt], cur + OFF_ALO + aOff + mt * (16 * BKP * 2) + ko);
            }
            #pragma unroll
            for (int np = 0; np < 4; np++) {
                ldsm4(bfh[np], cur + OFF_BHI + bOff + np * (16 * BKP * 2) + ko);
                ldsm4(bfl[np], cur + OFF_BLO + bOff + np * (16 * BKP * 2) + ko);
            }
            #pragma unroll
            for (int mt = 0; mt < 2; mt++)
                #pragma unroll
                for (int nt = 0; nt < 8; nt++) {
                    const uint32_t* bh = &bfh[nt >> 1][(nt & 1) * 2];
                    const uint32_t* bl = &bfl[nt >> 1][(nt & 1) * 2];
                    mma16816(acc[mt][nt], afh[mt], bh);
                    mma16816(acc[mt][nt], afh[mt], bl);
                    mma16816(acc[mt][nt], afl[mt], bh);
                }
        }

        if (kt + 1 < KT) stsA(nxt);
    }

    // epilogue: H only
    #pragma unroll
    for (int mt = 0; mt < 2; mt++) {
        int r0 = bm + wm + mt * 16 + (lane >> 2);
        int r1 = r0 + 8;
        #pragma unroll
        for (int nt = 0; nt < 8; nt++) {
            int cn = bn + wn + nt * 8 + (lane & 3) * 2;
            if (r0 < M)
                *(float2*)&H[(size_t)r0 * 256 + cn] = make_float2(acc[mt][nt][0], acc[mt][nt][1]);
            if (r1 < M)
                *(float2*)&H[(size_t)r1 * 256 + cn] = make_float2(acc[mt][nt][2], acc[mt][nt][3]);
        }
    }
}

// ---------------- CSR aggregation: warp per dst row, no atomics --------------
__global__ __launch_bounds__(256) void k_agg_csr(const float* __restrict__ h,
                                                 float* __restrict__ a) {
    int r = blockIdx.x * 8 + (threadIdx.x >> 5);
    if (r >= N_NODES) return;
    int lane = threadIdx.x & 31;
    float dr = g_dinv[r];
    float w0 = dr * dr;
    const float4* hr = (const float4*)(h + (size_t)r * 256);
    float4 v0 = hr[lane], v1 = hr[lane + 32];
    float4 a0 = make_float4(v0.x * w0, v0.y * w0, v0.z * w0, v0.w * w0);
    float4 a1 = make_float4(v1.x * w0, v1.y * w0, v1.z * w0, v1.w * w0);
    int beg = g_rowptr[r], end = g_rowptr[r + 1];
    for (int t = beg; t < end; t++) {
        int s = g_csrc[t];
        float w = g_dinv[s] * dr;
        const float4* hs = (const float4*)(h + (size_t)s * 256);
        float4 u0 = hs[lane], u1 = hs[lane + 32];
        a0.x += u0.x * w; a0.y += u0.y * w; a0.z += u0.z * w; a0.w += u0.w * w;
        a1.x += u1.x * w; a1.y += u1.y * w; a1.z += u1.z * w; a1.w += u1.w * w;
    }
    float4* ar = (float4*)(a + (size_t)r * 256);
    ar[lane] = a0;
    ar[lane + 32] = a1;
}

// ---------------- pooling: batch sorted -> binary search per graph -----------
__global__ void k_pool(const float* __restrict__ a, const float* __restrict__ b2,
                       float* __restrict__ out) {
    int g = blockIdx.x;
    __shared__ int sLo, sHi;
    if (threadIdx.x == 0) {
        int lo = 0, hi = N_NODES;
        while (lo < hi) { int mid = (lo + hi) >> 1; if (g_batch[mid] < g) lo = mid + 1; else hi = mid; }
        sLo = lo;
        hi = N_NODES;
        while (lo < hi) { int mid = (lo + hi) >> 1; if (g_batch[mid] < g + 1) lo = mid + 1; else hi = mid; }
        sHi = lo;
    }
    __syncthreads();
    int c = threadIdx.x;
    float sum = 0.0f;
    for (int v = sLo; v < sHi; v++) sum += a[(size_t)v * 256 + c];
    int cnt = sHi - sLo;
    out[(size_t)g * 256 + c] = (cnt > 0) ? (sum / (float)cnt + b2[c]) : 0.0f;
}

// ---------------- launcher ---------------------------------------------------
extern "C" void kernel_launch(void* const* d_in, const int* in_sizes, int n_in,
                              void* d_out, int out_size) {
    const float* x    = (const float*)d_in[0];
    const float* W1   = (const float*)d_in[1];
    const float* b1   = (const float*)d_in[2];
    const float* W2   = (const float*)d_in[3];
    const float* b2   = (const float*)d_in[4];
    const void*  ei   = d_in[5];
    const void*  bat  = d_in[6];
    float* out = (float*)d_out;

    float *ph, *pa;
    __nv_bfloat16 *pw1h, *pw1l, *pw2h, *pw2l;
    cudaGetSymbolAddress((void**)&ph, g_h);
    cudaGetSymbolAddress((void**)&pa, g_a);
    cudaGetSymbolAddress((void**)&pw1h, g_w1hi);
    cudaGetSymbolAddress((void**)&pw1l, g_w1lo);
    cudaGetSymbolAddress((void**)&pw2h, g_w2hi);
    cudaGetSymbolAddress((void**)&pw2l, g_w2lo);

    cudaFuncSetAttribute(k_gemm_tc<IN_CH, false>,
                         cudaFuncAttributeMaxDynamicSharedMemorySize, SMEM_DYN);
    cudaFuncSetAttribute(k_gemm_tc<HID_CH, true>,
                         cudaFuncAttributeMaxDynamicSharedMemorySize, SMEM_DYN);

    dim3 gemmGrid(2, (N_NODES + 127) / 128);     // N-tile fastest: twins share A in L2

    // launches 0..4 setup; launch 5 = GEMM1 (ncu -s 5 -c 1 profiles it)
    k_detect<<<1, 256>>>((const int*)ei);
    k_convert_all<<<(2 * N_EDGES + 255) / 256, 256>>>(ei, bat);
    k_deg_accum<<<(N_EDGES + 255) / 256, 256>>>();
    k_scan<<<1, 1024>>>();
    k_fill_wprep<<<(N_EDGES + 255) / 256, 256>>>(W1, W2);

    // layer 1
    k_gemm_tc<IN_CH, false><<<gemmGrid, 256, SMEM_DYN>>>(x, pw1h, pw1l, nullptr, ph, N_NODES);
    k_agg_csr<<<(N_NODES + 7) / 8, 256>>>(ph, pa);

    // layer 2 (relu(a + b1) fused into A load)
    k_gemm_tc<HID_CH, true><<<gemmGrid, 256, SMEM_DYN>>>(pa, pw2h, pw2l, b1, ph, N_NODES);
    k_agg_csr<<<(N_NODES + 7) / 8, 256>>>(ph, pa);

    k_pool<<<NUM_GRAPHS, 256>>>(pa, b2, out);
}

// round 5
// speedup vs baseline: 2.3603x; 1.0881x over previous
#include <cuda_runtime.h>
#include <cuda_bf16.h>
#include <cstdint>

#define N_NODES   200000
#define N_EDGES   400000
#define IN_CH     768
#define HID_CH    256
#define NUM_GRAPHS 8000

// ---------------- scratch (device globals: no allocations allowed) ----------
__device__ int   g_is64;
__device__ int   g_total;
__device__ int   g_edges[2 * N_EDGES];          // [src(E), dst(E)] as int32
__device__ int   g_batch[N_NODES];
__device__ int   g_indeg[N_NODES];
__device__ int   g_rowbeg[N_NODES];             // CSR range start (arbitrary order)
__device__ int   g_cursor[N_NODES];
__device__ int   g_csrc[N_EDGES];               // CSR-by-dst: src ids
__device__ float g_dinv[N_NODES];               // rsqrt(1 + indeg)
__device__ float g_h[(size_t)N_NODES * 256];    // GEMM output (pre-agg features)
__device__ float g_a[(size_t)N_NODES * 256];    // aggregated output
__device__ __nv_bfloat16 g_w1hi[256 * IN_CH];   // W^T hi/lo splits, [n][k] K-major
__device__ __nv_bfloat16 g_w1lo[256 * IN_CH];
__device__ __nv_bfloat16 g_w2hi[256 * HID_CH];
__device__ __nv_bfloat16 g_w2lo[256 * HID_CH];

// ---------------- setup ------------------------------------------------------
// detect int width + zero indeg + weight transpose/split (no edge deps)
__global__ void k_detect(const int* ei32) {
    __shared__ int any;
    if (threadIdx.x == 0) any = 0;
    __syncthreads();
    int idx = threadIdx.x * 3120 + 1;           // max 795601 < 800000 (safe if int32)
    if (ei32[idx] != 0) any = 1;
    __syncthreads();
    if (threadIdx.x == 0) { g_is64 = (any == 0) ? 1 : 0; g_total = 0; }
}

__global__ void k_wprep(const float* __restrict__ W1, const float* __restrict__ W2) {
    int i = blockIdx.x * blockDim.x + threadIdx.x;
    if (i < N_NODES) g_indeg[i] = 0;
    if (i < IN_CH * 256) {
        int k = i / 256, n = i % 256;
        float w = W1[i];
        __nv_bfloat16 h = __float2bfloat16_rn(w);
        g_w1hi[(size_t)n * IN_CH + k] = h;
        g_w1lo[(size_t)n * IN_CH + k] = __float2bfloat16_rn(w - __bfloat162float(h));
    } else {
        int j = i - IN_CH * 256;
        if (j < HID_CH * 256) {
            int k = j / 256, n = j % 256;
            float w = W2[j];
            __nv_bfloat16 h = __float2bfloat16_rn(w);
            g_w2hi[(size_t)n * HID_CH + k] = h;
            g_w2lo[(size_t)n * HID_CH + k] = __float2bfloat16_rn(w - __bfloat162float(h));
        }
    }
}

// convert edges+batch and accumulate in-degree (grid covers 2E)
__global__ void k_convert_deg(const void* ei, const void* bat) {
    int i = blockIdx.x * blockDim.x + threadIdx.x;
    bool is64 = (g_is64 != 0);
    if (i < N_NODES) {
        g_batch[i] = is64 ? (int)((const long long*)bat)[i] : ((const int*)bat)[i];
    }
    if (i < 2 * N_EDGES) {
        int v = is64 ? (int)((const long long*)ei)[i] : ((const int*)ei)[i];
        g_edges[i] = v;
        if (i >= N_EDGES) atomicAdd(&g_indeg[v], 1);   // dst half
    }
}

// order-free CSR range alloc + dinv (replaces the 198us serial scan)
__global__ void k_alloc() {
    int i = blockIdx.x * blockDim.x + threadIdx.x;
    if (i >= N_NODES) return;
    int d = g_indeg[i];
    int beg = atomicAdd(&g_total, d);           // uniform-addr -> REDUX aggregated
    g_rowbeg[i] = beg;
    g_cursor[i] = beg;
    g_dinv[i] = rsqrtf(1.0f + (float)d);
}

// CSR scatter
__global__ void k_fill() {
    int e = blockIdx.x * blockDim.x + threadIdx.x;
    if (e < N_EDGES) {
        int s = g_edges[e], d = g_edges[N_EDGES + e];
        int pos = atomicAdd(&g_cursor[d], 1);
        g_csrc[pos] = s;
    }
}

// ---------------- GEMM: mma.sync bf16 3-product split, 2-stage pipeline ------
__device__ __forceinline__ void ldsm4(uint32_t r[4], uint32_t addr) {
    asm volatile("ldmatrix.sync.aligned.m8n8.x4.shared.b16 {%0,%1,%2,%3}, [%4];"
        : "=r"(r[0]), "=r"(r[1]), "=r"(r[2]), "=r"(r[3]) : "r"(addr));
}
__device__ __forceinline__ void mma16816(float c[4], const uint32_t a[4], const uint32_t b[2]) {
    asm volatile(
        "mma.sync.aligned.m16n8k16.row.col.f32.bf16.bf16.f32 "
        "{%0,%1,%2,%3}, {%4,%5,%6,%7}, {%8,%9}, {%0,%1,%2,%3};"
        : "+f"(c[0]), "+f"(c[1]), "+f"(c[2]), "+f"(c[3])
        : "r"(a[0]), "r"(a[1]), "r"(a[2]), "r"(a[3]), "r"(b[0]), "r"(b[1]));
}
__device__ __forceinline__ void cpasync16(uint32_t dst, const void* src) {
    asm volatile("cp.async.cg.shared.global [%0], [%1], 16;" :: "r"(dst), "l"(src));
}
__device__ __forceinline__ uint32_t smem_u32(const void* p) {
    uint32_t a;
    asm("{ .reg .u64 t; cvta.to.shared.u64 t, %1; cvt.u32.u64 %0, t; }" : "=r"(a) : "l"(p));
    return a;
}

#define BKP 40                       // padded BK row (bf16): 80B stride
#define ST_BYTES (4 * 128 * BKP * 2) // 40960 per stage
#define OFF_AHI 0
#define OFF_ALO (128 * BKP * 2)
#define OFF_BHI (2 * 128 * BKP * 2)
#define OFF_BLO (3 * 128 * BKP * 2)
#define SMEM_DYN (2 * ST_BYTES)      // 81920

template<int K, bool FUSE>
__global__ __launch_bounds__(256) void k_gemm_tc(
    const float* __restrict__ A,
    const __nv_bfloat16* __restrict__ BHi, const __nv_bfloat16* __restrict__ BLo,
    const float* __restrict__ bias, float* __restrict__ H, int M)
{
    extern __shared__ __align__(16) char smem[];
    const uint32_t sb = smem_u32(smem);

    const int tid  = threadIdx.x;
    const int lane = tid & 31;
    const int wid  = tid >> 5;
    const int bn   = blockIdx.x * 128;
    const int bm   = blockIdx.y * 128;
    const int wm   = (wid & 3) * 32;
    const int wn   = (wid >> 2) * 64;

    const int gRow  = tid >> 1;
    const int half  = tid & 1;
    const bool aValid = (bm + gRow) < M;
    const float* Ap = A + (size_t)(bm + gRow) * K + half * 16;
    const __nv_bfloat16* BHp = BHi + (size_t)(bn + gRow) * K + half * 16;
    const __nv_bfloat16* BLp = BLo + (size_t)(bn + gRow) * K + half * 16;
    const uint32_t stsOff = (uint32_t)gRow * (BKP * 2) + half * 32;

    const uint32_t aOff = (uint32_t)(wm + (lane & 15)) * (BKP * 2) + ((lane >> 4) << 4);
    const uint32_t bOff = (uint32_t)(wn + (lane & 7) + ((lane >> 4) & 1) * 8) * (BKP * 2)
                        + (((lane >> 3) & 1) << 4);

    float acc[2][8][4];
    #pragma unroll
    for (int mt = 0; mt < 2; mt++)
        #pragma unroll
        for (int nt = 0; nt < 8; nt++)
            #pragma unroll
            for (int j = 0; j < 4; j++) acc[mt][nt][j] = 0.0f;

    constexpr int KT = K / 32;

    float4 aReg[4];
    auto loadA = [&](int kt) {
        #pragma unroll
        for (int i = 0; i < 4; i++) {
            float4 t = aValid ? *(const float4*)(Ap + kt * 32 + 4 * i)
                              : make_float4(0.f, 0.f, 0.f, 0.f);
            if constexpr (FUSE) {
                float4 bb = *(const float4*)(bias + kt * 32 + half * 16 + 4 * i);
                t.x = fmaxf(t.x + bb.x, 0.f); t.y = fmaxf(t.y + bb.y, 0.f);
                t.z = fmaxf(t.z + bb.z, 0.f); t.w = fmaxf(t.w + bb.w, 0.f);
                if (!aValid) t = make_float4(0.f, 0.f, 0.f, 0.f);
            }
            aReg[i] = t;
        }
    };
    auto stsA = [&](uint32_t stage) {
        uint32_t hw[8], lw[8];
        #pragma unroll
        for (int i = 0; i < 4; i++) {
            float4 v = aReg[i];
            __nv_bfloat16 b0 = __float2bfloat16_rn(v.x);
            __nv_bfloat16 b1 = __float2bfloat16_rn(v.y);
            __nv_bfloat16 b2 = __float2bfloat16_rn(v.z);
            __nv_bfloat16 b3 = __float2bfloat16_rn(v.w);
            __nv_bfloat162 h0; h0.x = b0; h0.y = b1;
            __nv_bfloat162 h1; h1.x = b2; h1.y = b3;
            __nv_bfloat162 l0;
            l0.x = __float2bfloat16_rn(v.x - __bfloat162float(b0));
            l0.y = __float2bfloat16_rn(v.y - __bfloat162float(b1));
            __nv_bfloat162 l1;
            l1.x = __float2bfloat16_rn(v.z - __bfloat162float(b2));
            l1.y = __float2bfloat16_rn(v.w - __bfloat162float(b3));
            hw[2 * i] = *(uint32_t*)&h0; hw[2 * i + 1] = *(uint32_t*)&h1;
            lw[2 * i] = *(uint32_t*)&l0; lw[2 * i + 1] = *(uint32_t*)&l1;
        }
        uint32_t d = stage + OFF_AHI + stsOff;
        asm volatile("st.shared.v4.b32 [%0], {%1,%2,%3,%4};"
                     :: "r"(d), "r"(hw[0]), "r"(hw[1]), "r"(hw[2]), "r"(hw[3]) : "memory");
        asm volatile("st.shared.v4.b32 [%0], {%1,%2,%3,%4};"
                     :: "r"(d + 16), "r"(hw[4]), "r"(hw[5]), "r"(hw[6]), "r"(hw[7]) : "memory");
        d = stage + OFF_ALO + stsOff;
        asm volatile("st.shared.v4.b32 [%0], {%1,%2,%3,%4};"
                     :: "r"(d), "r"(lw[0]), "r"(lw[1]), "r"(lw[2]), "r"(lw[3]) : "memory");
        asm volatile("st.shared.v4.b32 [%0], {%1,%2,%3,%4};"
                     :: "r"(d + 16), "r"(lw[4]), "r"(lw[5]), "r"(lw[6]), "r"(lw[7]) : "memory");
    };
    auto cpB = [&](int kt, uint32_t stage) {
        cpasync16(stage + OFF_BHI + stsOff,      BHp + kt * 32);
        cpasync16(stage + OFF_BHI + stsOff + 16, BHp + kt * 32 + 8);
        cpasync16(stage + OFF_BLO + stsOff,      BLp + kt * 32);
        cpasync16(stage + OFF_BLO + stsOff + 16, BLp + kt * 32 + 8);
        asm volatile("cp.async.commit_group;" ::: "memory");
    };

    loadA(0);
    cpB(0, sb);
    stsA(sb);

    for (int kt = 0; kt < KT; kt++) {
        const uint32_t cur = sb + (kt & 1) * ST_BYTES;
        const uint32_t nxt = sb + ((kt + 1) & 1) * ST_BYTES;

        asm volatile("cp.async.wait_group 0;" ::: "memory");
        __syncthreads();

        if (kt + 1 < KT) {
            loadA(kt + 1);
            cpB(kt + 1, nxt);
        }

        #pragma unroll
        for (int kk = 0; kk < 2; kk++) {
            const uint32_t ko = kk * 32;
            uint32_t afh[2][4], afl[2][4], bfh[4][4], bfl[4][4];
            #pragma unroll
            for (int mt = 0; mt < 2; mt++) {
                ldsm4(afh[mt], cur + OFF_AHI + aOff + mt * (16 * BKP * 2) + ko);
                ldsm4(afl[mt], cur + OFF_ALO + aOff + mt * (16 * BKP * 2) + ko);
            }
            #pragma unroll
            for (int np = 0; np < 4; np++) {
                ldsm4(bfh[np], cur + OFF_BHI + bOff + np * (16 * BKP * 2) + ko);
                ldsm4(bfl[np], cur + OFF_BLO + bOff + np * (16 * BKP * 2) + ko);
            }
            #pragma unroll
            for (int mt = 0; mt < 2; mt++)
                #pragma unroll
                for (int nt = 0; nt < 8; nt++) {
                    const uint32_t* bh = &bfh[nt >> 1][(nt & 1) * 2];
                    const uint32_t* bl = &bfl[nt >> 1][(nt & 1) * 2];
                    mma16816(acc[mt][nt], afh[mt], bh);
                    mma16816(acc[mt][nt], afh[mt], bl);
                    mma16816(acc[mt][nt], afl[mt], bh);
                }
        }

        if (kt + 1 < KT) stsA(nxt);
    }

    #pragma unroll
    for (int mt = 0; mt < 2; mt++) {
        int r0 = bm + wm + mt * 16 + (lane >> 2);
        int r1 = r0 + 8;
        #pragma unroll
        for (int nt = 0; nt < 8; nt++) {
            int cn = bn + wn + nt * 8 + (lane & 3) * 2;
            if (r0 < M)
                *(float2*)&H[(size_t)r0 * 256 + cn] = make_float2(acc[mt][nt][0], acc[mt][nt][1]);
            if (r1 < M)
                *(float2*)&H[(size_t)r1 * 256 + cn] = make_float2(acc[mt][nt][2], acc[mt][nt][3]);
        }
    }
}

// ---------------- CSR aggregation: warp per dst row, no atomics --------------
__global__ __launch_bounds__(256) void k_agg_csr(const float* __restrict__ h,
                                                 float* __restrict__ a) {
    int r = blockIdx.x * 8 + (threadIdx.x >> 5);
    if (r >= N_NODES) return;
    int lane = threadIdx.x & 31;
    float dr = g_dinv[r];
    float w0 = dr * dr;
    const float4* hr = (const float4*)(h + (size_t)r * 256);
    float4 v0 = hr[lane], v1 = hr[lane + 32];
    float4 a0 = make_float4(v0.x * w0, v0.y * w0, v0.z * w0, v0.w * w0);
    float4 a1 = make_float4(v1.x * w0, v1.y * w0, v1.z * w0, v1.w * w0);
    int beg = g_rowbeg[r], end = beg + g_indeg[r];
    for (int t = beg; t < end; t++) {
        int s = g_csrc[t];
        float w = g_dinv[s] * dr;
        const float4* hs = (const float4*)(h + (size_t)s * 256);
        float4 u0 = hs[lane], u1 = hs[lane + 32];
        a0.x += u0.x * w; a0.y += u0.y * w; a0.z += u0.z * w; a0.w += u0.w * w;
        a1.x += u1.x * w; a1.y += u1.y * w; a1.z += u1.z * w; a1.w += u1.w * w;
    }
    float4* ar = (float4*)(a + (size_t)r * 256);
    ar[lane] = a0;
    ar[lane + 32] = a1;
}

// ---------------- pooling: batch sorted -> binary search per graph -----------
__global__ void k_pool(const float* __restrict__ a, const float* __restrict__ b2,
                       float* __restrict__ out) {
    int g = blockIdx.x;
    __shared__ int sLo, sHi;
    if (threadIdx.x == 0) {
        int lo = 0, hi = N_NODES;
        while (lo < hi) { int mid = (lo + hi) >> 1; if (g_batch[mid] < g) lo = mid + 1; else hi = mid; }
        sLo = lo;
        hi = N_NODES;
        while (lo < hi) { int mid = (lo + hi) >> 1; if (g_batch[mid] < g + 1) lo = mid + 1; else hi = mid; }
        sHi = lo;
    }
    __syncthreads();
    int c = threadIdx.x;
    float sum = 0.0f;
    for (int v = sLo; v < sHi; v++) sum += a[(size_t)v * 256 + c];
    int cnt = sHi - sLo;
    out[(size_t)g * 256 + c] = (cnt > 0) ? (sum / (float)cnt + b2[c]) : 0.0f;
}

// ---------------- launcher ---------------------------------------------------
extern "C" void kernel_launch(void* const* d_in, const int* in_sizes, int n_in,
                              void* d_out, int out_size) {
    const float* x    = (const float*)d_in[0];
    const float* W1   = (const float*)d_in[1];
    const float* b1   = (const float*)d_in[2];
    const float* W2   = (const float*)d_in[3];
    const float* b2   = (const float*)d_in[4];
    const void*  ei   = d_in[5];
    const void*  bat  = d_in[6];
    float* out = (float*)d_out;

    float *ph, *pa;
    __nv_bfloat16 *pw1h, *pw1l, *pw2h, *pw2l;
    cudaGetSymbolAddress((void**)&ph, g_h);
    cudaGetSymbolAddress((void**)&pa, g_a);
    cudaGetSymbolAddress((void**)&pw1h, g_w1hi);
    cudaGetSymbolAddress((void**)&pw1l, g_w1lo);
    cudaGetSymbolAddress((void**)&pw2h, g_w2hi);
    cudaGetSymbolAddress((void**)&pw2l, g_w2lo);

    cudaFuncSetAttribute(k_gemm_tc<IN_CH, false>,
                         cudaFuncAttributeMaxDynamicSharedMemorySize, SMEM_DYN);
    cudaFuncSetAttribute(k_gemm_tc<HID_CH, true>,
                         cudaFuncAttributeMaxDynamicSharedMemorySize, SMEM_DYN);

    dim3 gemmGrid(2, (N_NODES + 127) / 128);     // N-tile fastest: twins share A in L2

    // launch index 3 = GEMM1 (ncu -s skip profiles launch index 3)
    k_detect<<<1, 256>>>((const int*)ei);                                 // 0
    k_wprep<<<((IN_CH + HID_CH) * 256 + 255) / 256, 256>>>(W1, W2);       // 1 (zeros indeg too)
    k_convert_deg<<<(2 * N_EDGES + 255) / 256, 256>>>(ei, bat);           // 2
    k_gemm_tc<IN_CH, false><<<gemmGrid, 256, SMEM_DYN>>>(                 // 3 <- profiled
        x, pw1h, pw1l, nullptr, ph, N_NODES);
    k_alloc<<<(N_NODES + 255) / 256, 256>>>();                            // 4
    k_fill<<<(N_EDGES + 255) / 256, 256>>>();                             // 5
    k_agg_csr<<<(N_NODES + 7) / 8, 256>>>(ph, pa);                        // 6
    k_gemm_tc<HID_CH, true><<<gemmGrid, 256, SMEM_DYN>>>(                 // 7
        pa, pw2h, pw2l, b1, ph, N_NODES);
    k_agg_csr<<<(N_NODES + 7) / 8, 256>>>(ph, pa);                        // 8
    k_pool<<<NUM_GRAPHS, 256>>>(pa, b2, out);                             // 9
}

// round 6
// speedup vs baseline: 2.8071x; 1.1893x over previous
#include <cuda_runtime.h>
#include <cuda_bf16.h>
#include <cstdint>

#define N_NODES   200000
#define N_EDGES   400000
#define IN_CH     768
#define HID_CH    256
#define NUM_GRAPHS 8000

// ---------------- scratch (device globals: no allocations allowed) ----------
__device__ int   g_is64;
__device__ int   g_total;
__device__ int   g_edges[2 * N_EDGES];          // [src(E), dst(E)] as int32
__device__ int   g_batch[N_NODES];
__device__ int   g_indeg[N_NODES];
__device__ int   g_rowbeg[N_NODES];             // CSR range start (arbitrary order)
__device__ int   g_cursor[N_NODES];
__device__ int   g_csrc[N_EDGES];               // CSR-by-dst: src ids
__device__ float g_dinv[N_NODES];               // rsqrt(1 + indeg)
__device__ float g_h[(size_t)N_NODES * 256];    // GEMM output (pre-agg features)
__device__ float g_a[(size_t)N_NODES * 256];    // aggregated output
__device__ __nv_bfloat16 g_w1hi[256 * IN_CH];   // W^T hi/lo splits, [n][k] K-major
__device__ __nv_bfloat16 g_w1lo[256 * IN_CH];
__device__ __nv_bfloat16 g_w2hi[256 * HID_CH];
__device__ __nv_bfloat16 g_w2lo[256 * HID_CH];

// ---------------- setup ------------------------------------------------------
__global__ void k_detect(const int* ei32) {
    __shared__ int any;
    if (threadIdx.x == 0) any = 0;
    __syncthreads();
    int idx = threadIdx.x * 3120 + 1;           // max 795601 < 800000 (safe if int32)
    if (ei32[idx] != 0) any = 1;
    __syncthreads();
    if (threadIdx.x == 0) { g_is64 = (any == 0) ? 1 : 0; g_total = 0; }
}

__global__ void k_wprep(const float* __restrict__ W1, const float* __restrict__ W2) {
    int i = blockIdx.x * blockDim.x + threadIdx.x;
    if (i < N_NODES) g_indeg[i] = 0;
    if (i < IN_CH * 256) {
        int k = i / 256, n = i % 256;
        float w = W1[i];
        __nv_bfloat16 h = __float2bfloat16_rn(w);
        g_w1hi[(size_t)n * IN_CH + k] = h;
        g_w1lo[(size_t)n * IN_CH + k] = __float2bfloat16_rn(w - __bfloat162float(h));
    } else {
        int j = i - IN_CH * 256;
        if (j < HID_CH * 256) {
            int k = j / 256, n = j % 256;
            float w = W2[j];
            __nv_bfloat16 h = __float2bfloat16_rn(w);
            g_w2hi[(size_t)n * HID_CH + k] = h;
            g_w2lo[(size_t)n * HID_CH + k] = __float2bfloat16_rn(w - __bfloat162float(h));
        }
    }
}

__global__ void k_convert_deg(const void* ei, const void* bat) {
    int i = blockIdx.x * blockDim.x + threadIdx.x;
    bool is64 = (g_is64 != 0);
    if (i < N_NODES) {
        g_batch[i] = is64 ? (int)((const long long*)bat)[i] : ((const int*)bat)[i];
    }
    if (i < 2 * N_EDGES) {
        int v = is64 ? (int)((const long long*)ei)[i] : ((const int*)ei)[i];
        g_edges[i] = v;
        if (i >= N_EDGES) atomicAdd(&g_indeg[v], 1);   // dst half
    }
}

__global__ void k_alloc() {
    int i = blockIdx.x * blockDim.x + threadIdx.x;
    if (i >= N_NODES) return;
    int d = g_indeg[i];
    int beg = atomicAdd(&g_total, d);           // uniform-addr -> REDUX aggregated
    g_rowbeg[i] = beg;
    g_cursor[i] = beg;
    g_dinv[i] = rsqrtf(1.0f + (float)d);
}

__global__ void k_fill() {
    int e = blockIdx.x * blockDim.x + threadIdx.x;
    if (e < N_EDGES) {
        int s = g_edges[e], d = g_edges[N_EDGES + e];
        int pos = atomicAdd(&g_cursor[d], 1);
        g_csrc[pos] = s;
    }
}

// ---------------- GEMM: mma.sync bf16 3-product split, 2-stage pipeline ------
__device__ __forceinline__ void ldsm4(uint32_t r[4], uint32_t addr) {
    asm volatile("ldmatrix.sync.aligned.m8n8.x4.shared.b16 {%0,%1,%2,%3}, [%4];"
        : "=r"(r[0]), "=r"(r[1]), "=r"(r[2]), "=r"(r[3]) : "r"(addr));
}
__device__ __forceinline__ void mma16816(float c[4], const uint32_t a[4], const uint32_t b[2]) {
    asm volatile(
        "mma.sync.aligned.m16n8k16.row.col.f32.bf16.bf16.f32 "
        "{%0,%1,%2,%3}, {%4,%5,%6,%7}, {%8,%9}, {%0,%1,%2,%3};"
        : "+f"(c[0]), "+f"(c[1]), "+f"(c[2]), "+f"(c[3])
        : "r"(a[0]), "r"(a[1]), "r"(a[2]), "r"(a[3]), "r"(b[0]), "r"(b[1]));
}
__device__ __forceinline__ void cpasync16(uint32_t dst, const void* src) {
    asm volatile("cp.async.cg.shared.global [%0], [%1], 16;" :: "r"(dst), "l"(src));
}
__device__ __forceinline__ uint32_t smem_u32(const void* p) {
    uint32_t a;
    asm("{ .reg .u64 t; cvta.to.shared.u64 t, %1; cvt.u32.u64 %0, t; }" : "=r"(a) : "l"(p));
    return a;
}

#define BKP 40                       // padded BK row (bf16): 80B stride
#define ST_BYTES (4 * 128 * BKP * 2) // 40960 per stage
#define OFF_AHI 0
#define OFF_ALO (128 * BKP * 2)
#define OFF_BHI (2 * 128 * BKP * 2)
#define OFF_BLO (3 * 128 * BKP * 2)
#define SMEM_DYN (2 * ST_BYTES)      // 81920 (2 CTAs = 160KB <= 228KB)

// 128x128 block, 8 warps (4M x 2N), warp tile 32x64. 2 CTAs/SM (reg-capped 128).
template<int K, bool FUSE>
__global__ __launch_bounds__(256, 2) void k_gemm_tc(
    const float* __restrict__ A,
    const __nv_bfloat16* __restrict__ BHi, const __nv_bfloat16* __restrict__ BLo,
    const float* __restrict__ bias, float* __restrict__ H, int M)
{
    extern __shared__ __align__(16) char smem[];
    const uint32_t sb = smem_u32(smem);

    const int tid  = threadIdx.x;
    const int lane = tid & 31;
    const int wid  = tid >> 5;
    const int bn   = blockIdx.x * 128;
    const int bm   = blockIdx.y * 128;
    const int wm   = (wid & 3) * 32;
    const int wn   = (wid >> 2) * 64;

    const int gRow  = tid >> 1;
    const int half  = tid & 1;
    const bool aValid = (bm + gRow) < M;
    const float* Ap = A + (size_t)(bm + gRow) * K + half * 16;
    const __nv_bfloat16* BHp = BHi + (size_t)(bn + gRow) * K + half * 16;
    const __nv_bfloat16* BLp = BLo + (size_t)(bn + gRow) * K + half * 16;
    const uint32_t stsOff = (uint32_t)gRow * (BKP * 2) + half * 32;

    const uint32_t aOff = (uint32_t)(wm + (lane & 15)) * (BKP * 2) + ((lane >> 4) << 4);
    const uint32_t bOff = (uint32_t)(wn + (lane & 7) + ((lane >> 4) & 1) * 8) * (BKP * 2)
                        + (((lane >> 3) & 1) << 4);

    float acc[2][8][4];
    #pragma unroll
    for (int mt = 0; mt < 2; mt++)
        #pragma unroll
        for (int nt = 0; nt < 8; nt++)
            #pragma unroll
            for (int j = 0; j < 4; j++) acc[mt][nt][j] = 0.0f;

    constexpr int KT = K / 32;

    float4 aReg[4];
    auto loadA = [&](int kt) {
        #pragma unroll
        for (int i = 0; i < 4; i++) {
            float4 t = aValid ? *(const float4*)(Ap + kt * 32 + 4 * i)
                              : make_float4(0.f, 0.f, 0.f, 0.f);
            if constexpr (FUSE) {
                float4 bb = *(const float4*)(bias + kt * 32 + half * 16 + 4 * i);
                t.x = fmaxf(t.x + bb.x, 0.f); t.y = fmaxf(t.y + bb.y, 0.f);
                t.z = fmaxf(t.z + bb.z, 0.f); t.w = fmaxf(t.w + bb.w, 0.f);
                if (!aValid) t = make_float4(0.f, 0.f, 0.f, 0.f);
            }
            aReg[i] = t;
        }
    };
    auto stsA = [&](uint32_t stage) {
        uint32_t hw[8], lw[8];
        #pragma unroll
        for (int i = 0; i < 4; i++) {
            float4 v = aReg[i];
            __nv_bfloat16 b0 = __float2bfloat16_rn(v.x);
            __nv_bfloat16 b1 = __float2bfloat16_rn(v.y);
            __nv_bfloat16 b2 = __float2bfloat16_rn(v.z);
            __nv_bfloat16 b3 = __float2bfloat16_rn(v.w);
            __nv_bfloat162 h0; h0.x = b0; h0.y = b1;
            __nv_bfloat162 h1; h1.x = b2; h1.y = b3;
            __nv_bfloat162 l0;
            l0.x = __float2bfloat16_rn(v.x - __bfloat162float(b0));
            l0.y = __float2bfloat16_rn(v.y - __bfloat162float(b1));
            __nv_bfloat162 l1;
            l1.x = __float2bfloat16_rn(v.z - __bfloat162float(b2));
            l1.y = __float2bfloat16_rn(v.w - __bfloat162float(b3));
            hw[2 * i] = *(uint32_t*)&h0; hw[2 * i + 1] = *(uint32_t*)&h1;
            lw[2 * i] = *(uint32_t*)&l0; lw[2 * i + 1] = *(uint32_t*)&l1;
        }
        uint32_t d = stage + OFF_AHI + stsOff;
        asm volatile("st.shared.v4.b32 [%0], {%1,%2,%3,%4};"
                     :: "r"(d), "r"(hw[0]), "r"(hw[1]), "r"(hw[2]), "r"(hw[3]) : "memory");
        asm volatile("st.shared.v4.b32 [%0], {%1,%2,%3,%4};"
                     :: "r"(d + 16), "r"(hw[4]), "r"(hw[5]), "r"(hw[6]), "r"(hw[7]) : "memory");
        d = stage + OFF_ALO + stsOff;
        asm volatile("st.shared.v4.b32 [%0], {%1,%2,%3,%4};"
                     :: "r"(d), "r"(lw[0]), "r"(lw[1]), "r"(lw[2]), "r"(lw[3]) : "memory");
        asm volatile("st.shared.v4.b32 [%0], {%1,%2,%3,%4};"
                     :: "r"(d + 16), "r"(lw[4]), "r"(lw[5]), "r"(lw[6]), "r"(lw[7]) : "memory");
    };
    auto cpB = [&](int kt, uint32_t stage) {
        cpasync16(stage + OFF_BHI + stsOff,      BHp + kt * 32);
        cpasync16(stage + OFF_BHI + stsOff + 16, BHp + kt * 32 + 8);
        cpasync16(stage + OFF_BLO + stsOff,      BLp + kt * 32);
        cpasync16(stage + OFF_BLO + stsOff + 16, BLp + kt * 32 + 8);
        asm volatile("cp.async.commit_group;" ::: "memory");
    };

    loadA(0);
    cpB(0, sb);
    stsA(sb);

    for (int kt = 0; kt < KT; kt++) {
        const uint32_t cur = sb + (kt & 1) * ST_BYTES;
        const uint32_t nxt = sb + ((kt + 1) & 1) * ST_BYTES;

        asm volatile("cp.async.wait_group 0;" ::: "memory");
        __syncthreads();

        if (kt + 1 < KT) {
            loadA(kt + 1);
            cpB(kt + 1, nxt);
        }

        #pragma unroll
        for (int kk = 0; kk < 2; kk++) {
            const uint32_t ko = kk * 32;
            uint32_t afh[2][4], afl[2][4];
            #pragma unroll
            for (int mt = 0; mt < 2; mt++) {
                ldsm4(afh[mt], cur + OFF_AHI + aOff + mt * (16 * BKP * 2) + ko);
                ldsm4(afl[mt], cur + OFF_ALO + aOff + mt * (16 * BKP * 2) + ko);
            }
            // B fragments loaded per np-pair: 8 live regs instead of 32
            #pragma unroll
            for (int np = 0; np < 4; np++) {
                uint32_t bfh[4], bfl[4];
                ldsm4(bfh, cur + OFF_BHI + bOff + np * (16 * BKP * 2) + ko);
                ldsm4(bfl, cur + OFF_BLO + bOff + np * (16 * BKP * 2) + ko);
                #pragma unroll
                for (int mt = 0; mt < 2; mt++)
                    #pragma unroll
                    for (int j = 0; j < 2; j++) {
                        const int nt = np * 2 + j;
                        mma16816(acc[mt][nt], afh[mt], &bfh[j * 2]);
                        mma16816(acc[mt][nt], afh[mt], &bfl[j * 2]);
                        mma16816(acc[mt][nt], afl[mt], &bfh[j * 2]);
                    }
            }
        }

        if (kt + 1 < KT) stsA(nxt);
    }

    #pragma unroll
    for (int mt = 0; mt < 2; mt++) {
        int r0 = bm + wm + mt * 16 + (lane >> 2);
        int r1 = r0 + 8;
        #pragma unroll
        for (int nt = 0; nt < 8; nt++) {
            int cn = bn + wn + nt * 8 + (lane & 3) * 2;
            if (r0 < M)
                *(float2*)&H[(size_t)r0 * 256 + cn] = make_float2(acc[mt][nt][0], acc[mt][nt][1]);
            if (r1 < M)
                *(float2*)&H[(size_t)r1 * 256 + cn] = make_float2(acc[mt][nt][2], acc[mt][nt][3]);
        }
    }
}

// ---------------- CSR aggregation: warp per dst row, no atomics --------------
__global__ __launch_bounds__(256) void k_agg_csr(const float* __restrict__ h,
                                                 float* __restrict__ a) {
    int r = blockIdx.x * 8 + (threadIdx.x >> 5);
    if (r >= N_NODES) return;
    int lane = threadIdx.x & 31;
    float dr = g_dinv[r];
    float w0 = dr * dr;
    const float4* hr = (const float4*)(h + (size_t)r * 256);
    float4 v0 = hr[lane], v1 = hr[lane + 32];
    float4 a0 = make_float4(v0.x * w0, v0.y * w0, v0.z * w0, v0.w * w0);
    float4 a1 = make_float4(v1.x * w0, v1.y * w0, v1.z * w0, v1.w * w0);
    int beg = g_rowbeg[r], end = beg + g_indeg[r];
    for (int t = beg; t < end; t++) {
        int s = g_csrc[t];
        float w = g_dinv[s] * dr;
        const float4* hs = (const float4*)(h + (size_t)s * 256);
        float4 u0 = hs[lane], u1 = hs[lane + 32];
        a0.x += u0.x * w; a0.y += u0.y * w; a0.z += u0.z * w; a0.w += u0.w * w;
        a1.x += u1.x * w; a1.y += u1.y * w; a1.z += u1.z * w; a1.w += u1.w * w;
    }
    float4* ar = (float4*)(a + (size_t)r * 256);
    ar[lane] = a0;
    ar[lane + 32] = a1;
}

// ---------------- pooling: batch sorted -> binary search per graph -----------
__global__ void k_pool(const float* __restrict__ a, const float* __restrict__ b2,
                       float* __restrict__ out) {
    int g = blockIdx.x;
    __shared__ int sLo, sHi;
    if (threadIdx.x == 0) {
        int lo = 0, hi = N_NODES;
        while (lo < hi) { int mid = (lo + hi) >> 1; if (g_batch[mid] < g) lo = mid + 1; else hi = mid; }
        sLo = lo;
        hi = N_NODES;
        while (lo < hi) { int mid = (lo + hi) >> 1; if (g_batch[mid] < g + 1) lo = mid + 1; else hi = mid; }
        sHi = lo;
    }
    __syncthreads();
    int c = threadIdx.x;
    float sum = 0.0f;
    for (int v = sLo; v < sHi; v++) sum += a[(size_t)v * 256 + c];
    int cnt = sHi - sLo;
    out[(size_t)g * 256 + c] = (cnt > 0) ? (sum / (float)cnt + b2[c]) : 0.0f;
}

// ---------------- launcher ---------------------------------------------------
extern "C" void kernel_launch(void* const* d_in, const int* in_sizes, int n_in,
                              void* d_out, int out_size) {
    const float* x    = (const float*)d_in[0];
    const float* W1   = (const float*)d_in[1];
    const float* b1   = (const float*)d_in[2];
    const float* W2   = (const float*)d_in[3];
    const float* b2   = (const float*)d_in[4];
    const void*  ei   = d_in[5];
    const void*  bat  = d_in[6];
    float* out = (float*)d_out;

    float *ph, *pa;
    __nv_bfloat16 *pw1h, *pw1l, *pw2h, *pw2l;
    cudaGetSymbolAddress((void**)&ph, g_h);
    cudaGetSymbolAddress((void**)&pa, g_a);
    cudaGetSymbolAddress((void**)&pw1h, g_w1hi);
    cudaGetSymbolAddress((void**)&pw1l, g_w1lo);
    cudaGetSymbolAddress((void**)&pw2h, g_w2hi);
    cudaGetSymbolAddress((void**)&pw2l, g_w2lo);

    cudaFuncSetAttribute(k_gemm_tc<IN_CH, false>,
                         cudaFuncAttributeMaxDynamicSharedMemorySize, SMEM_DYN);
    cudaFuncSetAttribute(k_gemm_tc<HID_CH, true>,
                         cudaFuncAttributeMaxDynamicSharedMemorySize, SMEM_DYN);

    dim3 gemmGrid(2, (N_NODES + 127) / 128);     // N-tile fastest: twins share A in L2

    // launch index 3 = GEMM1 (ncu profiles launch index 3)
    k_detect<<<1, 256>>>((const int*)ei);                                 // 0
    k_wprep<<<((IN_CH + HID_CH) * 256 + 255) / 256, 256>>>(W1, W2);       // 1 (zeros indeg too)
    k_convert_deg<<<(2 * N_EDGES + 255) / 256, 256>>>(ei, bat);           // 2
    k_gemm_tc<IN_CH, false><<<gemmGrid, 256, SMEM_DYN>>>(                 // 3 <- profiled
        x, pw1h, pw1l, nullptr, ph, N_NODES);
    k_alloc<<<(N_NODES + 255) / 256, 256>>>();                            // 4
    k_fill<<<(N_EDGES + 255) / 256, 256>>>();                             // 5
    k_agg_csr<<<(N_NODES + 7) / 8, 256>>>(ph, pa);                        // 6
    k_gemm_tc<HID_CH, true><<<gemmGrid, 256, SMEM_DYN>>>(                 // 7
        pa, pw2h, pw2l, b1, ph, N_NODES);
    k_agg_csr<<<(N_NODES + 7) / 8, 256>>>(ph, pa);                        // 8
    k_pool<<<NUM_GRAPHS, 256>>>(pa, b2, out);                             // 9
}